// round 5
// baseline (speedup 1.0000x reference)
#include <cuda_runtime.h>
#include <math.h>
#include <stdint.h>

// Problem constants
#define PD   768        // model dim
#define NB   8          // batch
#define NP   1024       // seq len
#define NH   12         // heads
#define NKV  6          // kv heads
#define HD   64         // head dim
#define BPROWS (NB*NP)          // 8192
#define KVDIM  (NKV*HD)         // 384
#define YLEN   (NP*HD)          // 65536
#define MTOT   (NH*YLEN)        // 786432

// ---------------- scratch (static device memory; no allocations) -------------
__device__ float pgqa_Q[BPROWS*PD];      // scaled q, [B*P, 768]
__device__ float pgqa_K[BPROWS*KVDIM];   // [B*P, 384]
__device__ float pgqa_V[BPROWS*KVDIM];
__device__ float pgqa_Att[BPROWS*PD];    // attention out, [B*P, 768] (col = h*64+d)
__device__ float pgqa_X2[BPROWS*PD];     // att after noise subtraction
__device__ float pgqa_M[MTOT];           // regenerated uniform matrix [12, 65536]
__device__ float pgqa_rmean[NB*NH];
__device__ float pgqa_rstd[NB*NH];
__device__ float pgqa_mmean[NH];
__device__ float pgqa_mistd[NH];

// ---------------- JAX threefry2x32, key = (0, 42) ----------------------------
__device__ __forceinline__ void pgqa_threefry(unsigned x0, unsigned x1,
                                              unsigned& o0, unsigned& o1) {
    const unsigned ks0 = 0u, ks1 = 42u, ks2 = 0x1BD11BDAu ^ 42u;
    x0 += ks0; x1 += ks1;
#define PGQA_R(r) { x0 += x1; x1 = (x1 << (r)) | (x1 >> (32 - (r))); x1 ^= x0; }
    PGQA_R(13) PGQA_R(15) PGQA_R(26) PGQA_R(6)
    x0 += ks1; x1 += ks2 + 1u;
    PGQA_R(17) PGQA_R(29) PGQA_R(16) PGQA_R(24)
    x0 += ks2; x1 += ks0 + 2u;
    PGQA_R(13) PGQA_R(15) PGQA_R(26) PGQA_R(6)
    x0 += ks0; x1 += ks1 + 3u;
    PGQA_R(17) PGQA_R(29) PGQA_R(16) PGQA_R(24)
    x0 += ks1; x1 += ks2 + 4u;
    PGQA_R(13) PGQA_R(15) PGQA_R(26) PGQA_R(6)
    x0 += ks2; x1 += ks0 + 5u;
#undef PGQA_R
    o0 = x0; o1 = x1;
}

__device__ __forceinline__ float pgqa_uniform(unsigned bits) {
    return __uint_as_float((bits >> 9) | 0x3f800000u) - 1.0f;
}

// JAX *partitionable* threefry bits for 32-bit draws at linear index i:
//   counts = iota(uint64); x0 = hi32(i) = 0, x1 = lo32(i) = i
//   (o0, o1) = threefry2x32(key, (x0, x1)); 32-bit draw = o0 ^ o1 (XOR fold)
__device__ __forceinline__ float pgqa_m_at(unsigned i) {
    unsigned o0, o1;
    pgqa_threefry(0u, i, o0, o1);
    return pgqa_uniform(o0 ^ o1);
}

// ---------------- generic tiled fp32 GEMM: C = alpha*(A@B) + bias ------------
// A: [M,K] row-major, B: [K,N] row-major. BM=BN=64, BK=16, 256 threads, 4x4/thr.
__global__ void pgqa_gemm(const float* __restrict__ A, const float* __restrict__ Bm,
                          const float* __restrict__ bias, float* __restrict__ C,
                          int M, int N, int K, float alpha) {
    __shared__ __align__(16) float As[16][68];
    __shared__ __align__(16) float Bs[16][68];
    const int t  = threadIdx.x;
    const int tx = t & 15, ty = t >> 4;
    const int row0 = blockIdx.y * 64, col0 = blockIdx.x * 64;
    float acc[4][4] = {};
    for (int k0 = 0; k0 < K; k0 += 16) {
        {   // A tile 64x16 -> As[k][m] (transposed on store)
            int r = t >> 2;              // 0..63
            int kg = (t & 3) * 4;        // 0,4,8,12
            float4 a4 = *(const float4*)(A + (size_t)(row0 + r) * K + k0 + kg);
            As[kg + 0][r] = a4.x; As[kg + 1][r] = a4.y;
            As[kg + 2][r] = a4.z; As[kg + 3][r] = a4.w;
        }
        {   // B tile 16x64 -> Bs[k][n]
            int kk = t >> 4;
            int cg = (t & 15) * 4;
            *(float4*)&Bs[kk][cg] = *(const float4*)(Bm + (size_t)(k0 + kk) * N + col0 + cg);
        }
        __syncthreads();
#pragma unroll
        for (int kk = 0; kk < 16; kk++) {
            float4 a4 = *(const float4*)&As[kk][ty * 4];
            float4 b4 = *(const float4*)&Bs[kk][tx * 4];
            float a[4] = {a4.x, a4.y, a4.z, a4.w};
            float b[4] = {b4.x, b4.y, b4.z, b4.w};
#pragma unroll
            for (int i = 0; i < 4; i++)
#pragma unroll
                for (int j = 0; j < 4; j++)
                    acc[i][j] += a[i] * b[j];
        }
        __syncthreads();
    }
#pragma unroll
    for (int i = 0; i < 4; i++) {
        int r = row0 + ty * 4 + i;
#pragma unroll
        for (int j = 0; j < 4; j++) {
            int c = col0 + tx * 4 + j;
            float v = acc[i][j] * alpha;
            if (bias) v += bias[c];
            C[(size_t)r * N + c] = v;
        }
    }
}

// ---------------- flash-style GQA attention ----------------------------------
// grid (P/64, B*H); block 256 = 8 warps; warp w owns q-rows 8w..8w+7, lane owns
// output columns {2l, 2l+1}. Q pre-scaled by HD^-0.5.
__global__ void pgqa_attn(const float* __restrict__ Q, const float* __restrict__ K,
                          const float* __restrict__ V, float* __restrict__ Out) {
    extern __shared__ float sm[];
    float* Qs = sm;               // 64*68
    float* Ks = sm + 64 * 68;     // reused for P tile
    float* Vs = sm + 2 * 64 * 68;

    const int tid = threadIdx.x;
    const int warp = tid >> 5, lane = tid & 31;
    const int b = blockIdx.y / NH, h = blockIdx.y % NH, kv = h >> 1;
    const int q0 = blockIdx.x * 64;

    const float* Qg = Q + ((size_t)b * NP + q0) * PD + h * HD;
    const float* Kg = K + (size_t)b * NP * KVDIM + kv * HD;
    const float* Vg = V + (size_t)b * NP * KVDIM + kv * HD;

    for (int i = tid; i < 64 * 16; i += 256) {
        int r = i >> 4, c4 = (i & 15) * 4;
        *(float4*)&Qs[r * 68 + c4] = *(const float4*)(Qg + (size_t)r * PD + c4);
    }

    float m_i[8], l_i[8], o0[8], o1[8];
#pragma unroll
    for (int r = 0; r < 8; r++) { m_i[r] = -1e30f; l_i[r] = 0.f; o0[r] = 0.f; o1[r] = 0.f; }
    const int d0 = lane * 2, d1 = lane * 2 + 1;
    const int qr0 = warp * 8;

    for (int tk = 0; tk < NP / 64; tk++) {
        __syncthreads();   // prior tile's P/V reads done (also covers Q load)
        for (int i = tid; i < 64 * 16; i += 256) {
            int r = i >> 4, c4 = (i & 15) * 4;
            *(float4*)&Ks[r * 68 + c4] = *(const float4*)(Kg + (size_t)(tk * 64 + r) * KVDIM + c4);
            *(float4*)&Vs[r * 68 + c4] = *(const float4*)(Vg + (size_t)(tk * 64 + r) * KVDIM + c4);
        }
        __syncthreads();

        // S = Q K^T for this warp's 8 rows x lane's 2 key-cols
        float s0[8], s1[8];
#pragma unroll
        for (int r = 0; r < 8; r++) { s0[r] = 0.f; s1[r] = 0.f; }
#pragma unroll 4
        for (int d = 0; d < 64; d += 4) {
            float4 k0 = *(const float4*)&Ks[d0 * 68 + d];
            float4 k1 = *(const float4*)&Ks[d1 * 68 + d];
#pragma unroll
            for (int r = 0; r < 8; r++) {
                float4 q4 = *(const float4*)&Qs[(qr0 + r) * 68 + d];
                s0[r] += q4.x * k0.x + q4.y * k0.y + q4.z * k0.z + q4.w * k0.w;
                s1[r] += q4.x * k1.x + q4.y * k1.y + q4.z * k1.z + q4.w * k1.w;
            }
        }
        __syncthreads();   // everyone done reading Ks -> reuse as P

        // online softmax per row; write P into Ks region
#pragma unroll
        for (int r = 0; r < 8; r++) {
            float mx = fmaxf(s0[r], s1[r]);
#pragma unroll
            for (int off = 16; off; off >>= 1) mx = fmaxf(mx, __shfl_xor_sync(~0u, mx, off));
            float mnew = fmaxf(m_i[r], mx);
            float corr = __expf(m_i[r] - mnew);
            float p0 = __expf(s0[r] - mnew);
            float p1 = __expf(s1[r] - mnew);
            float ps = p0 + p1;
#pragma unroll
            for (int off = 16; off; off >>= 1) ps += __shfl_xor_sync(~0u, ps, off);
            l_i[r] = l_i[r] * corr + ps;
            m_i[r] = mnew;
            o0[r] *= corr; o1[r] *= corr;
            *(float2*)&Ks[(qr0 + r) * 68 + d0] = make_float2(p0, p1);
        }
        __syncthreads();

        // O += P @ V
#pragma unroll 4
        for (int k = 0; k < 64; k += 4) {
            float v00 = Vs[(k + 0) * 68 + d0], v01 = Vs[(k + 0) * 68 + d1];
            float v10 = Vs[(k + 1) * 68 + d0], v11 = Vs[(k + 1) * 68 + d1];
            float v20 = Vs[(k + 2) * 68 + d0], v21 = Vs[(k + 2) * 68 + d1];
            float v30 = Vs[(k + 3) * 68 + d0], v31 = Vs[(k + 3) * 68 + d1];
#pragma unroll
            for (int r = 0; r < 8; r++) {
                float4 p4 = *(const float4*)&Ks[(qr0 + r) * 68 + k];
                o0[r] += p4.x * v00 + p4.y * v10 + p4.z * v20 + p4.w * v30;
                o1[r] += p4.x * v01 + p4.y * v11 + p4.z * v21 + p4.w * v31;
            }
        }
    }

    float* Og = Out + ((size_t)b * NP + q0) * PD + h * HD;
#pragma unroll
    for (int r = 0; r < 8; r++) {
        float inv = 1.f / l_i[r];
        *(float2*)(Og + (size_t)(qr0 + r) * PD + d0) = make_float2(o0[r] * inv, o1[r] * inv);
    }
}

// -------- generate M (12 rows x 65536, partitionable threefry) + row stats ---
__global__ void pgqa_mgen_stats() {
    const int h = blockIdx.x;      // 0..11
    const int tid = threadIdx.x;   // 256
    double s = 0.0, s2 = 0.0;
    for (unsigned c = tid; c < YLEN; c += 256) {
        unsigned i = (unsigned)h * YLEN + c;
        float mv = pgqa_m_at(i);
        if (c == (unsigned)(h & 1)) mv = 0.f;   // zeroed diagonal element (col = g)
        pgqa_M[i] = mv;
        s += mv; s2 += (double)mv * mv;
    }
    __shared__ double shs[256], shs2[256];
    shs[tid] = s; shs2[tid] = s2; __syncthreads();
    for (int st = 128; st > 0; st >>= 1) {
        if (tid < st) { shs[tid] += shs[tid + st]; shs2[tid] += shs2[tid + st]; }
        __syncthreads();
    }
    if (tid == 0) {
        double n = (double)YLEN;
        double mean = shs[0] / n;
        double var = (shs2[0] - shs[0] * shs[0] / n) / (n - 1.0);
        double sd = sqrt(var > 0.0 ? var : 0.0);
        if (sd == 0.0) sd = 1.0;
        pgqa_mmean[h] = (float)mean;
        pgqa_mistd[h] = (float)(1.0 / sd);
    }
}

// ---------------- per (b,h) row stats of att ---------------------------------
__global__ void pgqa_rstats(const float* __restrict__ Att) {
    const int bh = blockIdx.x, b = bh / NH, h = bh % NH;
    const int tid = threadIdx.x;   // 256
    const float* base = Att + (size_t)b * NP * PD + h * HD;
    const int d = tid & 63, p0 = tid >> 6;
    double s = 0.0, s2 = 0.0;
    for (int p = p0; p < NP; p += 4) {
        float v = base[(size_t)p * PD + d];
        s += v; s2 += (double)v * v;
    }
    __shared__ double shs[256], shs2[256];
    shs[tid] = s; shs2[tid] = s2; __syncthreads();
    for (int st = 128; st > 0; st >>= 1) {
        if (tid < st) { shs[tid] += shs[tid + st]; shs2[tid] += shs2[tid + st]; }
        __syncthreads();
    }
    if (tid == 0) {
        double n = (double)YLEN;
        double mean = shs[0] / n;
        double var = (shs2[0] - shs[0] * shs[0] / n) / (n - 1.0);
        pgqa_rmean[bh] = (float)mean;
        pgqa_rstd[bh] = (float)sqrt(var > 0.0 ? var : 0.0);
    }
}

// ---------------- noise subtraction: X2 = att - (Z*r_std + r_mean) -----------
// one thread per element; M read from the precomputed buffer.
__global__ void pgqa_noise(const float* __restrict__ Att, float* __restrict__ X2) {
    size_t idx = (size_t)blockIdx.x * 256 + threadIdx.x;   // < 8192*768
    int j = (int)(idx % PD);                 // column in [0,768)
    size_t bp = idx / PD;
    int h = j >> 6, d = j & 63;              // head 0..11, dim 0..63
    int p = (int)(bp % NP);
    int b = (int)(bp / NP);
    unsigned c = (unsigned)(p * 64 + d);     // column in M row
    float m = pgqa_M[(unsigned)h * YLEN + c];
    float z = (m - pgqa_mmean[h]) * pgqa_mistd[h];
    int bh = b * NH + h;
    X2[idx] = Att[idx] - (z * pgqa_rstd[bh] + pgqa_rmean[bh]);
}

// ---------------- launcher ---------------------------------------------------
extern "C" void kernel_launch(void* const* d_in, const int* in_sizes, int n_in,
                              void* d_out, int out_size) {
    const float* x  = (const float*)d_in[0];
    const float* Wq = (const float*)d_in[1];
    const float* Wk = (const float*)d_in[2];
    const float* Wv = (const float*)d_in[3];
    const float* Wp = (const float*)d_in[4];
    const float* bp = (const float*)d_in[5];
    float* out = (float*)d_out;

    float *Qb, *Kb, *Vb, *Ab, *X2b;
    cudaGetSymbolAddress((void**)&Qb,  pgqa_Q);
    cudaGetSymbolAddress((void**)&Kb,  pgqa_K);
    cudaGetSymbolAddress((void**)&Vb,  pgqa_V);
    cudaGetSymbolAddress((void**)&Ab,  pgqa_Att);
    cudaGetSymbolAddress((void**)&X2b, pgqa_X2);

    const int ATTN_SMEM = 3 * 64 * 68 * 4;   // 52224 B > 48KB default
    cudaFuncSetAttribute(pgqa_attn, cudaFuncAttributeMaxDynamicSharedMemorySize, ATTN_SMEM);

    // q/k/v projections (q pre-scaled by 1/sqrt(64))
    pgqa_gemm<<<dim3(PD / 64, BPROWS / 64), 256>>>(x, Wq, nullptr, Qb, BPROWS, PD, PD, 0.125f);
    pgqa_gemm<<<dim3(KVDIM / 64, BPROWS / 64), 256>>>(x, Wk, nullptr, Kb, BPROWS, KVDIM, PD, 1.0f);
    pgqa_gemm<<<dim3(KVDIM / 64, BPROWS / 64), 256>>>(x, Wv, nullptr, Vb, BPROWS, KVDIM, PD, 1.0f);

    // attention
    pgqa_attn<<<dim3(NP / 64, NB * NH), 256, ATTN_SMEM>>>(Qb, Kb, Vb, Ab);

    // noise: M generation + stats, att row stats, subtraction
    pgqa_mgen_stats<<<NH, 256>>>();
    pgqa_rstats<<<NB * NH, 256>>>(Ab);
    pgqa_noise<<<(BPROWS * PD) / 256, 256>>>(Ab, X2b);

    // output projection (+bias)
    pgqa_gemm<<<dim3(PD / 64, BPROWS / 64), 256>>>(X2b, Wp, bp, out, BPROWS, PD, PD, 1.0f);
}

// round 8
// speedup vs baseline: 1.4289x; 1.4289x over previous
#include <cuda_runtime.h>
#include <math.h>
#include <stdint.h>

// Problem constants
#define PD   768        // model dim
#define NB   8          // batch
#define NP   1024       // seq len
#define NH   12         // heads
#define NKV  6          // kv heads
#define HD   64         // head dim
#define BPROWS (NB*NP)          // 8192
#define KVDIM  (NKV*HD)         // 384
#define YLEN   (NP*HD)          // 65536
#define MTOT   (NH*YLEN)        // 786432

// ---------------- scratch (static device memory; no allocations) -------------
__device__ float pgqa_Q[BPROWS*PD];      // scaled q, [B*P, 768]
__device__ float pgqa_K[BPROWS*KVDIM];   // [B*P, 384]
__device__ float pgqa_V[BPROWS*KVDIM];
__device__ float pgqa_Att[BPROWS*PD];    // attention out, [B*P, 768] (col = h*64+d)
__device__ float pgqa_X2[BPROWS*PD];     // att after noise subtraction
__device__ float pgqa_M[MTOT];           // regenerated uniform matrix [12, 65536]
__device__ float pgqa_rmean[NB*NH];
__device__ float pgqa_rstd[NB*NH];
__device__ float pgqa_mmean[NH];
__device__ float pgqa_mistd[NH];

// ---------------- JAX threefry2x32, key = (0, 42) ----------------------------
__device__ __forceinline__ void pgqa_threefry(unsigned x0, unsigned x1,
                                              unsigned& o0, unsigned& o1) {
    const unsigned ks0 = 0u, ks1 = 42u, ks2 = 0x1BD11BDAu ^ 42u;
    x0 += ks0; x1 += ks1;
#define PGQA_R(r) { x0 += x1; x1 = (x1 << (r)) | (x1 >> (32 - (r))); x1 ^= x0; }
    PGQA_R(13) PGQA_R(15) PGQA_R(26) PGQA_R(6)
    x0 += ks1; x1 += ks2 + 1u;
    PGQA_R(17) PGQA_R(29) PGQA_R(16) PGQA_R(24)
    x0 += ks2; x1 += ks0 + 2u;
    PGQA_R(13) PGQA_R(15) PGQA_R(26) PGQA_R(6)
    x0 += ks0; x1 += ks1 + 3u;
    PGQA_R(17) PGQA_R(29) PGQA_R(16) PGQA_R(24)
    x0 += ks1; x1 += ks2 + 4u;
    PGQA_R(13) PGQA_R(15) PGQA_R(26) PGQA_R(6)
    x0 += ks2; x1 += ks0 + 5u;
#undef PGQA_R
    o0 = x0; o1 = x1;
}
__device__ __forceinline__ float pgqa_uniform(unsigned bits) {
    return __uint_as_float((bits >> 9) | 0x3f800000u) - 1.0f;
}
// JAX partitionable threefry: draw = fold(o0 ^ o1) at count (0, i)
__device__ __forceinline__ float pgqa_m_at(unsigned i) {
    unsigned o0, o1;
    pgqa_threefry(0u, i, o0, o1);
    return pgqa_uniform(o0 ^ o1);
}

__device__ __forceinline__ unsigned pgqa_tf32r(float f) {
    unsigned u; asm("cvt.rna.tf32.f32 %0, %1;" : "=r"(u) : "f"(f)); return u;
}
__device__ __forceinline__ void pgqa_mma_tf32(float& c0, float& c1, float& c2, float& c3,
                                              unsigned a0, unsigned a1, unsigned a2, unsigned a3,
                                              unsigned b0, unsigned b1) {
    asm volatile(
        "mma.sync.aligned.m16n8k8.row.col.f32.tf32.tf32.f32 "
        "{%0,%1,%2,%3}, {%4,%5,%6,%7}, {%8,%9}, {%0,%1,%2,%3};"
        : "+f"(c0), "+f"(c1), "+f"(c2), "+f"(c3)
        : "r"(a0), "r"(a1), "r"(a2), "r"(a3), "r"(b0), "r"(b1));
}

// ============== mma.sync tf32 GEMM: C = alpha*(A@B) + bias ===================
// A: [M,K] row-major fp32; B: [K,N] row-major fp32. Block tile 128x128, BK=32,
// 256 threads = 8 warps, warp grid 2x4, warp tile 64x32 (4 m-tiles x 4 n-tiles
// of m16n8k8). Smem strides chosen conflict-free for the fragment loads.
#define GAS 36     // As stride: bank = (36m+k)%32 = (4m+k)%32 -> 32 distinct
#define GBS 136    // Bs stride: bank = (136k+n)%32 = (8k+n)%32 -> 32 distinct

__global__ __launch_bounds__(256)
void pgqa_gemm_mma(const float* __restrict__ A, const float* __restrict__ B,
                   const float* __restrict__ bias, float* __restrict__ C,
                   int N, int K, float alpha) {
    __shared__ unsigned As[128 * GAS];   // [m][k] tf32 bits
    __shared__ unsigned Bs[32 * GBS];    // [k][n] tf32 bits
    const int t = threadIdx.x, warp = t >> 5, lane = t & 31;
    const int g = lane >> 2, q = lane & 3;           // groupID, thread-in-group
    const int wm = (warp >> 2) * 64, wn = (warp & 3) * 32;
    const int m0 = blockIdx.y * 128, col0 = blockIdx.x * 128;

    float acc[4][4][4];
#pragma unroll
    for (int i = 0; i < 4; i++)
#pragma unroll
        for (int j = 0; j < 4; j++) {
            acc[i][j][0] = 0.f; acc[i][j][1] = 0.f;
            acc[i][j][2] = 0.f; acc[i][j][3] = 0.f;
        }

    for (int kc0 = 0; kc0 < K; kc0 += 32) {
        __syncthreads();
        // A tile: 128 x 32  (1024 float4 / 256 thr = 4 each)
#pragma unroll
        for (int i = 0; i < 4; i++) {
            int idx = t + (i << 8);
            int r = idx >> 3, j = (idx & 7) << 2;
            float4 v = *(const float4*)(A + (size_t)(m0 + r) * K + kc0 + j);
            unsigned* dst = &As[r * GAS + j];
            dst[0] = pgqa_tf32r(v.x); dst[1] = pgqa_tf32r(v.y);
            dst[2] = pgqa_tf32r(v.z); dst[3] = pgqa_tf32r(v.w);
        }
        // B tile: 32 x 128
#pragma unroll
        for (int i = 0; i < 4; i++) {
            int idx = t + (i << 8);
            int r = idx >> 5, j = (idx & 31) << 2;
            float4 v = *(const float4*)(B + (size_t)(kc0 + r) * N + col0 + j);
            unsigned* dst = &Bs[r * GBS + j];
            dst[0] = pgqa_tf32r(v.x); dst[1] = pgqa_tf32r(v.y);
            dst[2] = pgqa_tf32r(v.z); dst[3] = pgqa_tf32r(v.w);
        }
        __syncthreads();

#pragma unroll
        for (int k8 = 0; k8 < 32; k8 += 8) {
            unsigned a[4][4];
#pragma unroll
            for (int mt = 0; mt < 4; mt++) {
                const unsigned* Ar = &As[(wm + mt * 16 + g) * GAS + k8 + q];
                a[mt][0] = Ar[0];                 // (g,      q)
                a[mt][1] = Ar[8 * GAS];           // (g+8,    q)
                a[mt][2] = Ar[4];                 // (g,      q+4)
                a[mt][3] = Ar[8 * GAS + 4];       // (g+8,    q+4)
            }
#pragma unroll
            for (int nt = 0; nt < 4; nt++) {
                const unsigned* Br = &Bs[(k8 + q) * GBS + wn + nt * 8 + g];
                unsigned b0 = Br[0];              // (k=q,   n=g)
                unsigned b1 = Br[4 * GBS];        // (k=q+4, n=g)
#pragma unroll
                for (int mt = 0; mt < 4; mt++)
                    pgqa_mma_tf32(acc[mt][nt][0], acc[mt][nt][1],
                                  acc[mt][nt][2], acc[mt][nt][3],
                                  a[mt][0], a[mt][1], a[mt][2], a[mt][3], b0, b1);
            }
        }
    }

    // epilogue
#pragma unroll
    for (int mt = 0; mt < 4; mt++) {
        int r0 = m0 + wm + mt * 16 + g;
#pragma unroll
        for (int nt = 0; nt < 4; nt++) {
            int c = col0 + wn + nt * 8 + q * 2;
            float b0 = 0.f, b1 = 0.f;
            if (bias) { b0 = bias[c]; b1 = bias[c + 1]; }
            *(float2*)(C + (size_t)r0 * N + c) =
                make_float2(acc[mt][nt][0] * alpha + b0, acc[mt][nt][1] * alpha + b1);
            *(float2*)(C + (size_t)(r0 + 8) * N + c) =
                make_float2(acc[mt][nt][2] * alpha + b0, acc[mt][nt][3] * alpha + b1);
        }
    }
}

// ---------------- flash-style GQA attention (fp32 SIMT) -----------------------
__global__ void pgqa_attn(const float* __restrict__ Q, const float* __restrict__ K,
                          const float* __restrict__ V, float* __restrict__ Out) {
    extern __shared__ float sm[];
    float* Qs = sm;               // 64*68
    float* Ks = sm + 64 * 68;     // reused for P tile
    float* Vs = sm + 2 * 64 * 68;

    const int tid = threadIdx.x;
    const int warp = tid >> 5, lane = tid & 31;
    const int b = blockIdx.y / NH, h = blockIdx.y % NH, kv = h >> 1;
    const int q0 = blockIdx.x * 64;

    const float* Qg = Q + ((size_t)b * NP + q0) * PD + h * HD;
    const float* Kg = K + (size_t)b * NP * KVDIM + kv * HD;
    const float* Vg = V + (size_t)b * NP * KVDIM + kv * HD;

    for (int i = tid; i < 64 * 16; i += 256) {
        int r = i >> 4, c4 = (i & 15) * 4;
        *(float4*)&Qs[r * 68 + c4] = *(const float4*)(Qg + (size_t)r * PD + c4);
    }

    float m_i[8], l_i[8], o0[8], o1[8];
#pragma unroll
    for (int r = 0; r < 8; r++) { m_i[r] = -1e30f; l_i[r] = 0.f; o0[r] = 0.f; o1[r] = 0.f; }
    const int d0 = lane * 2, d1 = lane * 2 + 1;
    const int qr0 = warp * 8;

    for (int tk = 0; tk < NP / 64; tk++) {
        __syncthreads();
        for (int i = tid; i < 64 * 16; i += 256) {
            int r = i >> 4, c4 = (i & 15) * 4;
            *(float4*)&Ks[r * 68 + c4] = *(const float4*)(Kg + (size_t)(tk * 64 + r) * KVDIM + c4);
            *(float4*)&Vs[r * 68 + c4] = *(const float4*)(Vg + (size_t)(tk * 64 + r) * KVDIM + c4);
        }
        __syncthreads();

        float s0[8], s1[8];
#pragma unroll
        for (int r = 0; r < 8; r++) { s0[r] = 0.f; s1[r] = 0.f; }
#pragma unroll 4
        for (int d = 0; d < 64; d += 4) {
            float4 k0 = *(const float4*)&Ks[d0 * 68 + d];
            float4 k1 = *(const float4*)&Ks[d1 * 68 + d];
#pragma unroll
            for (int r = 0; r < 8; r++) {
                float4 q4 = *(const float4*)&Qs[(qr0 + r) * 68 + d];
                s0[r] += q4.x * k0.x + q4.y * k0.y + q4.z * k0.z + q4.w * k0.w;
                s1[r] += q4.x * k1.x + q4.y * k1.y + q4.z * k1.z + q4.w * k1.w;
            }
        }
        __syncthreads();

#pragma unroll
        for (int r = 0; r < 8; r++) {
            float mx = fmaxf(s0[r], s1[r]);
#pragma unroll
            for (int off = 16; off; off >>= 1) mx = fmaxf(mx, __shfl_xor_sync(~0u, mx, off));
            float mnew = fmaxf(m_i[r], mx);
            float corr = __expf(m_i[r] - mnew);
            float p0 = __expf(s0[r] - mnew);
            float p1 = __expf(s1[r] - mnew);
            float ps = p0 + p1;
#pragma unroll
            for (int off = 16; off; off >>= 1) ps += __shfl_xor_sync(~0u, ps, off);
            l_i[r] = l_i[r] * corr + ps;
            m_i[r] = mnew;
            o0[r] *= corr; o1[r] *= corr;
            *(float2*)&Ks[(qr0 + r) * 68 + d0] = make_float2(p0, p1);
        }
        __syncthreads();

#pragma unroll 4
        for (int k = 0; k < 64; k += 4) {
            float v00 = Vs[(k + 0) * 68 + d0], v01 = Vs[(k + 0) * 68 + d1];
            float v10 = Vs[(k + 1) * 68 + d0], v11 = Vs[(k + 1) * 68 + d1];
            float v20 = Vs[(k + 2) * 68 + d0], v21 = Vs[(k + 2) * 68 + d1];
            float v30 = Vs[(k + 3) * 68 + d0], v31 = Vs[(k + 3) * 68 + d1];
#pragma unroll
            for (int r = 0; r < 8; r++) {
                float4 p4 = *(const float4*)&Ks[(qr0 + r) * 68 + k];
                o0[r] += p4.x * v00 + p4.y * v10 + p4.z * v20 + p4.w * v30;
                o1[r] += p4.x * v01 + p4.y * v11 + p4.z * v21 + p4.w * v31;
            }
        }
    }

    float* Og = Out + ((size_t)b * NP + q0) * PD + h * HD;
#pragma unroll
    for (int r = 0; r < 8; r++) {
        float inv = 1.f / l_i[r];
        *(float2*)(Og + (size_t)(qr0 + r) * PD + d0) = make_float2(o0[r] * inv, o1[r] * inv);
    }
}

// -------- generate M (12 rows x 65536, partitionable threefry) + row stats ---
__global__ void pgqa_mgen_stats() {
    const int h = blockIdx.x;      // 0..11
    const int tid = threadIdx.x;   // 256
    double s = 0.0, s2 = 0.0;
    for (unsigned c = tid; c < YLEN; c += 256) {
        unsigned i = (unsigned)h * YLEN + c;
        float mv = pgqa_m_at(i);
        if (c == (unsigned)(h & 1)) mv = 0.f;   // zeroed diagonal element
        pgqa_M[i] = mv;
        s += mv; s2 += (double)mv * mv;
    }
    __shared__ double shs[256], shs2[256];
    shs[tid] = s; shs2[tid] = s2; __syncthreads();
    for (int st = 128; st > 0; st >>= 1) {
        if (tid < st) { shs[tid] += shs[tid + st]; shs2[tid] += shs2[tid + st]; }
        __syncthreads();
    }
    if (tid == 0) {
        double n = (double)YLEN;
        double mean = shs[0] / n;
        double var = (shs2[0] - shs[0] * shs[0] / n) / (n - 1.0);
        double sd = sqrt(var > 0.0 ? var : 0.0);
        if (sd == 0.0) sd = 1.0;
        pgqa_mmean[h] = (float)mean;
        pgqa_mistd[h] = (float)(1.0 / sd);
    }
}

// ---------------- per (b,h) row stats of att ---------------------------------
__global__ void pgqa_rstats(const float* __restrict__ Att) {
    const int bh = blockIdx.x, b = bh / NH, h = bh % NH;
    const int tid = threadIdx.x;   // 256
    const float* base = Att + (size_t)b * NP * PD + h * HD;
    const int d = tid & 63, p0 = tid >> 6;
    double s = 0.0, s2 = 0.0;
    for (int p = p0; p < NP; p += 4) {
        float v = base[(size_t)p * PD + d];
        s += v; s2 += (double)v * v;
    }
    __shared__ double shs[256], shs2[256];
    shs[tid] = s; shs2[tid] = s2; __syncthreads();
    for (int st = 128; st > 0; st >>= 1) {
        if (tid < st) { shs[tid] += shs[tid + st]; shs2[tid] += shs2[tid + st]; }
        __syncthreads();
    }
    if (tid == 0) {
        double n = (double)YLEN;
        double mean = shs[0] / n;
        double var = (shs2[0] - shs[0] * shs[0] / n) / (n - 1.0);
        pgqa_rmean[bh] = (float)mean;
        pgqa_rstd[bh] = (float)sqrt(var > 0.0 ? var : 0.0);
    }
}

// ---------------- noise subtraction: X2 = att - (Z*r_std + r_mean) -----------
__global__ void pgqa_noise(const float* __restrict__ Att, float* __restrict__ X2) {
    size_t idx = (size_t)blockIdx.x * 256 + threadIdx.x;   // < 8192*768
    int j = (int)(idx % PD);
    size_t bp = idx / PD;
    int h = j >> 6, d = j & 63;
    int p = (int)(bp % NP);
    int b = (int)(bp / NP);
    unsigned c = (unsigned)(p * 64 + d);
    float m = pgqa_M[(unsigned)h * YLEN + c];
    float z = (m - pgqa_mmean[h]) * pgqa_mistd[h];
    int bh = b * NH + h;
    X2[idx] = Att[idx] - (z * pgqa_rstd[bh] + pgqa_rmean[bh]);
}

// ---------------- launcher ---------------------------------------------------
extern "C" void kernel_launch(void* const* d_in, const int* in_sizes, int n_in,
                              void* d_out, int out_size) {
    const float* x  = (const float*)d_in[0];
    const float* Wq = (const float*)d_in[1];
    const float* Wk = (const float*)d_in[2];
    const float* Wv = (const float*)d_in[3];
    const float* Wp = (const float*)d_in[4];
    const float* bp = (const float*)d_in[5];
    float* out = (float*)d_out;

    float *Qb, *Kb, *Vb, *Ab, *X2b;
    cudaGetSymbolAddress((void**)&Qb,  pgqa_Q);
    cudaGetSymbolAddress((void**)&Kb,  pgqa_K);
    cudaGetSymbolAddress((void**)&Vb,  pgqa_V);
    cudaGetSymbolAddress((void**)&Ab,  pgqa_Att);
    cudaGetSymbolAddress((void**)&X2b, pgqa_X2);

    const int ATTN_SMEM = 3 * 64 * 68 * 4;   // 52224 B
    cudaFuncSetAttribute(pgqa_attn, cudaFuncAttributeMaxDynamicSharedMemorySize, ATTN_SMEM);

    // q/k/v projections on tensor cores (q pre-scaled by 1/sqrt(64))
    pgqa_gemm_mma<<<dim3(PD / 128, BPROWS / 128), 256>>>(x, Wq, nullptr, Qb, PD, PD, 0.125f);
    pgqa_gemm_mma<<<dim3(KVDIM / 128, BPROWS / 128), 256>>>(x, Wk, nullptr, Kb, KVDIM, PD, 1.0f);
    pgqa_gemm_mma<<<dim3(KVDIM / 128, BPROWS / 128), 256>>>(x, Wv, nullptr, Vb, KVDIM, PD, 1.0f);

    // attention
    pgqa_attn<<<dim3(NP / 64, NB * NH), 256, ATTN_SMEM>>>(Qb, Kb, Vb, Ab);

    // noise: M generation + stats, att row stats, subtraction
    pgqa_mgen_stats<<<NH, 256>>>();
    pgqa_rstats<<<NB * NH, 256>>>(Ab);
    pgqa_noise<<<(BPROWS * PD) / 256, 256>>>(Ab, X2b);

    // output projection (+bias) on tensor cores
    pgqa_gemm_mma<<<dim3(PD / 128, BPROWS / 128), 256>>>(X2b, Wp, bp, out, PD, PD, 1.0f);
}

// round 9
// speedup vs baseline: 2.1102x; 1.4768x over previous
#include <cuda_runtime.h>
#include <math.h>
#include <stdint.h>

// Problem constants
#define PD   768        // model dim
#define NB   8          // batch
#define NP   1024       // seq len
#define NH   12         // heads
#define NKV  6          // kv heads
#define HD   64         // head dim
#define BPROWS (NB*NP)          // 8192
#define KVDIM  (NKV*HD)         // 384
#define YLEN   (NP*HD)          // 65536
#define MTOT   (NH*YLEN)        // 786432

// ---------------- scratch (static device memory; no allocations) -------------
__device__ float pgqa_Q[BPROWS*PD];      // scaled q, [B*P, 768]
__device__ float pgqa_K[BPROWS*KVDIM];   // [B*P, 384]
__device__ float pgqa_V[BPROWS*KVDIM];
__device__ float pgqa_Att[BPROWS*PD];    // attention out, [B*P, 768] (col = h*64+d)
__device__ float pgqa_M[MTOT];           // regenerated uniform matrix [12, 65536]
__device__ float pgqa_rmean[NB*NH];
__device__ float pgqa_rstd[NB*NH];
__device__ float pgqa_mmean[NH];
__device__ float pgqa_mistd[NH];
__device__ double pgqa_msum[NH];
__device__ double pgqa_msum2[NH];

// ---------------- JAX threefry2x32, key = (0, 42) ----------------------------
__device__ __forceinline__ void pgqa_threefry(unsigned x0, unsigned x1,
                                              unsigned& o0, unsigned& o1) {
    const unsigned ks0 = 0u, ks1 = 42u, ks2 = 0x1BD11BDAu ^ 42u;
    x0 += ks0; x1 += ks1;
#define PGQA_R(r) { x0 += x1; x1 = (x1 << (r)) | (x1 >> (32 - (r))); x1 ^= x0; }
    PGQA_R(13) PGQA_R(15) PGQA_R(26) PGQA_R(6)
    x0 += ks1; x1 += ks2 + 1u;
    PGQA_R(17) PGQA_R(29) PGQA_R(16) PGQA_R(24)
    x0 += ks2; x1 += ks0 + 2u;
    PGQA_R(13) PGQA_R(15) PGQA_R(26) PGQA_R(6)
    x0 += ks0; x1 += ks1 + 3u;
    PGQA_R(17) PGQA_R(29) PGQA_R(16) PGQA_R(24)
    x0 += ks1; x1 += ks2 + 4u;
    PGQA_R(13) PGQA_R(15) PGQA_R(26) PGQA_R(6)
    x0 += ks2; x1 += ks0 + 5u;
#undef PGQA_R
    o0 = x0; o1 = x1;
}
__device__ __forceinline__ float pgqa_uniform(unsigned bits) {
    return __uint_as_float((bits >> 9) | 0x3f800000u) - 1.0f;
}
// JAX partitionable threefry: draw = fold(o0 ^ o1) at count (0, i)
__device__ __forceinline__ float pgqa_m_at(unsigned i) {
    unsigned o0, o1;
    pgqa_threefry(0u, i, o0, o1);
    return pgqa_uniform(o0 ^ o1);
}

__device__ __forceinline__ unsigned pgqa_tf32r(float f) {
    unsigned u; asm("cvt.rna.tf32.f32 %0, %1;" : "=r"(u) : "f"(f)); return u;
}
__device__ __forceinline__ void pgqa_mma_tf32(float& c0, float& c1, float& c2, float& c3,
                                              unsigned a0, unsigned a1, unsigned a2, unsigned a3,
                                              unsigned b0, unsigned b1) {
    asm volatile(
        "mma.sync.aligned.m16n8k8.row.col.f32.tf32.tf32.f32 "
        "{%0,%1,%2,%3}, {%4,%5,%6,%7}, {%8,%9}, {%0,%1,%2,%3};"
        : "+f"(c0), "+f"(c1), "+f"(c2), "+f"(c3)
        : "r"(a0), "r"(a1), "r"(a2), "r"(a3), "r"(b0), "r"(b1));
}

// ============== mma.sync tf32 GEMM: C = alpha*(A@B) + bias ===================
// Block tile 128x128, BK=32, 256 thr = 8 warps (2x4), warp tile 64x32.
// FUSE_NOISE: A is pgqa_Att; apply X2 = A - (Z*r_std + r_mean) during A load.
#define GAS 36     // As stride: bank = (4m+k)%32 -> conflict-free
#define GBS 136    // Bs stride: bank = (8k+n)%32 -> conflict-free

template<bool FUSE_NOISE>
__global__ __launch_bounds__(256)
void pgqa_gemm_mma(const float* __restrict__ A, const float* __restrict__ B,
                   const float* __restrict__ bias, float* __restrict__ C,
                   int N, int K, float alpha) {
    __shared__ unsigned As[128 * GAS];   // [m][k] tf32 bits
    __shared__ unsigned Bs[32 * GBS];    // [k][n] tf32 bits
    const int t = threadIdx.x, warp = t >> 5, lane = t & 31;
    const int g = lane >> 2, q = lane & 3;
    const int wm = (warp >> 2) * 64, wn = (warp & 3) * 32;
    const int m0 = blockIdx.y * 128, col0 = blockIdx.x * 128;

    float acc[4][4][4];
#pragma unroll
    for (int i = 0; i < 4; i++)
#pragma unroll
        for (int j = 0; j < 4; j++) {
            acc[i][j][0] = 0.f; acc[i][j][1] = 0.f;
            acc[i][j][2] = 0.f; acc[i][j][3] = 0.f;
        }

    for (int kc0 = 0; kc0 < K; kc0 += 32) {
        __syncthreads();
        // A tile: 128 x 32
#pragma unroll
        for (int i = 0; i < 4; i++) {
            int idx = t + (i << 8);
            int r = idx >> 3, j = (idx & 7) << 2;
            float4 v = *(const float4*)(A + (size_t)(m0 + r) * K + kc0 + j);
            if (FUSE_NOISE) {
                int c = kc0 + j;                 // 4-aligned, within one head seg
                int hh = c >> 6, dd = c & 63;
                int rg = m0 + r;
                int pp = rg & (NP - 1);
                int bh = (rg >> 10) * NH + hh;
                float4 mv = *(const float4*)(pgqa_M + ((size_t)hh << 16) + (pp << 6) + dd);
                float im = pgqa_mmean[hh], is = pgqa_mistd[hh];
                float rs = pgqa_rstd[bh], rm = pgqa_rmean[bh];
                v.x -= (mv.x - im) * is * rs + rm;
                v.y -= (mv.y - im) * is * rs + rm;
                v.z -= (mv.z - im) * is * rs + rm;
                v.w -= (mv.w - im) * is * rs + rm;
            }
            unsigned* dst = &As[r * GAS + j];
            dst[0] = pgqa_tf32r(v.x); dst[1] = pgqa_tf32r(v.y);
            dst[2] = pgqa_tf32r(v.z); dst[3] = pgqa_tf32r(v.w);
        }
        // B tile: 32 x 128
#pragma unroll
        for (int i = 0; i < 4; i++) {
            int idx = t + (i << 8);
            int r = idx >> 5, j = (idx & 31) << 2;
            float4 v = *(const float4*)(B + (size_t)(kc0 + r) * N + col0 + j);
            unsigned* dst = &Bs[r * GBS + j];
            dst[0] = pgqa_tf32r(v.x); dst[1] = pgqa_tf32r(v.y);
            dst[2] = pgqa_tf32r(v.z); dst[3] = pgqa_tf32r(v.w);
        }
        __syncthreads();

#pragma unroll
        for (int k8 = 0; k8 < 32; k8 += 8) {
            unsigned a[4][4];
#pragma unroll
            for (int mt = 0; mt < 4; mt++) {
                const unsigned* Ar = &As[(wm + mt * 16 + g) * GAS + k8 + q];
                a[mt][0] = Ar[0];
                a[mt][1] = Ar[8 * GAS];
                a[mt][2] = Ar[4];
                a[mt][3] = Ar[8 * GAS + 4];
            }
#pragma unroll
            for (int nt = 0; nt < 4; nt++) {
                const unsigned* Br = &Bs[(k8 + q) * GBS + wn + nt * 8 + g];
                unsigned b0 = Br[0];
                unsigned b1 = Br[4 * GBS];
#pragma unroll
                for (int mt = 0; mt < 4; mt++)
                    pgqa_mma_tf32(acc[mt][nt][0], acc[mt][nt][1],
                                  acc[mt][nt][2], acc[mt][nt][3],
                                  a[mt][0], a[mt][1], a[mt][2], a[mt][3], b0, b1);
            }
        }
    }

#pragma unroll
    for (int mt = 0; mt < 4; mt++) {
        int r0 = m0 + wm + mt * 16 + g;
#pragma unroll
        for (int nt = 0; nt < 4; nt++) {
            int c = col0 + wn + nt * 8 + q * 2;
            float b0 = 0.f, b1 = 0.f;
            if (bias) { b0 = bias[c]; b1 = bias[c + 1]; }
            *(float2*)(C + (size_t)r0 * N + c) =
                make_float2(acc[mt][nt][0] * alpha + b0, acc[mt][nt][1] * alpha + b1);
            *(float2*)(C + (size_t)(r0 + 8) * N + c) =
                make_float2(acc[mt][nt][2] * alpha + b0, acc[mt][nt][3] * alpha + b1);
        }
    }
}

// ============== mma.sync tf32 flash GQA attention ============================
// grid (P/64, B*H); 128 thr = 4 warps; warp owns 16 q-rows. K-tile = 64.
// Q held in A-fragments (regs); K in smem K-major; V transposed in smem;
// P round-trips through smem as tf32 bits.
#define ATS 68   // smem stride: bank = (4row+col)%32 -> conflict-free frags

__global__ __launch_bounds__(128)
void pgqa_attn_mma(const float* __restrict__ Q, const float* __restrict__ K,
                   const float* __restrict__ V, float* __restrict__ Out) {
    extern __shared__ unsigned smu[];
    unsigned* Ks = smu;                  // [64][ATS]  K[kpos][d]
    unsigned* Vt = smu + 64 * ATS;       // [64][ATS]  V^T[d][kpos]
    unsigned* Ps = smu + 2 * 64 * ATS;   // [64][ATS]  Q staging, then P[q][kpos]

    const int t = threadIdx.x, warp = t >> 5, lane = t & 31;
    const int g = lane >> 2, qd = lane & 3;
    const int b = blockIdx.y / NH, h = blockIdx.y % NH, kvh = h >> 1;
    const int q0 = blockIdx.x * 64, wm = warp * 16;

    const float* Qg = Q + ((size_t)(b * NP + q0)) * PD + h * HD;
    const float* Kg = K + (size_t)b * NP * KVDIM + kvh * HD;
    const float* Vg = V + (size_t)b * NP * KVDIM + kvh * HD;

    // stage Q tile (64x64) -> Ps as tf32
    {
        int r = t >> 1, c0 = (t & 1) * 32;
        const float* src = Qg + (size_t)r * PD + c0;
#pragma unroll
        for (int j = 0; j < 8; j++) {
            float4 v = *(const float4*)(src + j * 4);
            unsigned* dst = &Ps[r * ATS + c0 + j * 4];
            dst[0] = pgqa_tf32r(v.x); dst[1] = pgqa_tf32r(v.y);
            dst[2] = pgqa_tf32r(v.z); dst[3] = pgqa_tf32r(v.w);
        }
    }
    __syncthreads();
    unsigned qa[8][4];
#pragma unroll
    for (int k8 = 0; k8 < 8; k8++) {
        const unsigned* A0 = &Ps[(wm + g) * ATS + k8 * 8 + qd];
        const unsigned* A1 = &Ps[(wm + g + 8) * ATS + k8 * 8 + qd];
        qa[k8][0] = A0[0]; qa[k8][1] = A1[0]; qa[k8][2] = A0[4]; qa[k8][3] = A1[4];
    }
    __syncthreads();

    float oacc[8][4];
#pragma unroll
    for (int nt = 0; nt < 8; nt++) {
        oacc[nt][0] = 0.f; oacc[nt][1] = 0.f; oacc[nt][2] = 0.f; oacc[nt][3] = 0.f;
    }
    float mr0 = -1e30f, mr1 = -1e30f, lr0 = 0.f, lr1 = 0.f;

    for (int tk = 0; tk < NP / 64; tk++) {
        // load K tile (K-major) and V tile (transposed)
        {
            int r = t >> 1, c0 = (t & 1) * 32;
            const float* ksrc = Kg + (size_t)(tk * 64 + r) * KVDIM + c0;
            const float* vsrc = Vg + (size_t)(tk * 64 + r) * KVDIM + c0;
#pragma unroll
            for (int j = 0; j < 8; j++) {
                float4 v = *(const float4*)(ksrc + j * 4);
                unsigned* dst = &Ks[r * ATS + c0 + j * 4];
                dst[0] = pgqa_tf32r(v.x); dst[1] = pgqa_tf32r(v.y);
                dst[2] = pgqa_tf32r(v.z); dst[3] = pgqa_tf32r(v.w);
                float4 w = *(const float4*)(vsrc + j * 4);
                int d0 = c0 + j * 4;
                Vt[(d0 + 0) * ATS + r] = pgqa_tf32r(w.x);
                Vt[(d0 + 1) * ATS + r] = pgqa_tf32r(w.y);
                Vt[(d0 + 2) * ATS + r] = pgqa_tf32r(w.z);
                Vt[(d0 + 3) * ATS + r] = pgqa_tf32r(w.w);
            }
        }
        __syncthreads();

        // S = Q K^T  (C-frag: c0,c1 = row g cols 2qd,2qd+1; c2,c3 = row g+8)
        float sacc[8][4];
#pragma unroll
        for (int nt = 0; nt < 8; nt++) {
            sacc[nt][0] = 0.f; sacc[nt][1] = 0.f; sacc[nt][2] = 0.f; sacc[nt][3] = 0.f;
        }
#pragma unroll
        for (int nt = 0; nt < 8; nt++) {
            const unsigned* Kr = &Ks[(nt * 8 + g) * ATS];
#pragma unroll
            for (int k8 = 0; k8 < 8; k8++) {
                unsigned b0 = Kr[k8 * 8 + qd];
                unsigned b1 = Kr[k8 * 8 + qd + 4];
                pgqa_mma_tf32(sacc[nt][0], sacc[nt][1], sacc[nt][2], sacc[nt][3],
                              qa[k8][0], qa[k8][1], qa[k8][2], qa[k8][3], b0, b1);
            }
        }

        // online softmax (rows g and g+8); quad lanes xor 1,2 share a row
        float mx0 = fmaxf(sacc[0][0], sacc[0][1]);
        float mx1 = fmaxf(sacc[0][2], sacc[0][3]);
#pragma unroll
        for (int nt = 1; nt < 8; nt++) {
            mx0 = fmaxf(mx0, fmaxf(sacc[nt][0], sacc[nt][1]));
            mx1 = fmaxf(mx1, fmaxf(sacc[nt][2], sacc[nt][3]));
        }
        mx0 = fmaxf(mx0, __shfl_xor_sync(~0u, mx0, 1));
        mx0 = fmaxf(mx0, __shfl_xor_sync(~0u, mx0, 2));
        mx1 = fmaxf(mx1, __shfl_xor_sync(~0u, mx1, 1));
        mx1 = fmaxf(mx1, __shfl_xor_sync(~0u, mx1, 2));
        float mn0 = fmaxf(mr0, mx0), mn1 = fmaxf(mr1, mx1);
        float corr0 = __expf(mr0 - mn0), corr1 = __expf(mr1 - mn1);
        float s0 = 0.f, s1 = 0.f;
        unsigned* P0 = &Ps[(wm + g) * ATS + qd * 2];
        unsigned* P1 = &Ps[(wm + g + 8) * ATS + qd * 2];
#pragma unroll
        for (int nt = 0; nt < 8; nt++) {
            float p0 = __expf(sacc[nt][0] - mn0);
            float p1 = __expf(sacc[nt][1] - mn0);
            float p2 = __expf(sacc[nt][2] - mn1);
            float p3 = __expf(sacc[nt][3] - mn1);
            s0 += p0 + p1; s1 += p2 + p3;
            P0[nt * 8 + 0] = pgqa_tf32r(p0); P0[nt * 8 + 1] = pgqa_tf32r(p1);
            P1[nt * 8 + 0] = pgqa_tf32r(p2); P1[nt * 8 + 1] = pgqa_tf32r(p3);
            oacc[nt][0] *= corr0; oacc[nt][1] *= corr0;
            oacc[nt][2] *= corr1; oacc[nt][3] *= corr1;
        }
        s0 += __shfl_xor_sync(~0u, s0, 1); s0 += __shfl_xor_sync(~0u, s0, 2);
        s1 += __shfl_xor_sync(~0u, s1, 1); s1 += __shfl_xor_sync(~0u, s1, 2);
        lr0 = lr0 * corr0 + s0; lr1 = lr1 * corr1 + s1;
        mr0 = mn0; mr1 = mn1;
        __syncthreads();

        // O += P V   (A-frags from Ps, B-frags from Vt)
#pragma unroll
        for (int k8 = 0; k8 < 8; k8++) {
            const unsigned* A0 = &Ps[(wm + g) * ATS + k8 * 8 + qd];
            const unsigned* A1 = &Ps[(wm + g + 8) * ATS + k8 * 8 + qd];
            unsigned pa0 = A0[0], pa1 = A1[0], pa2 = A0[4], pa3 = A1[4];
#pragma unroll
            for (int nt = 0; nt < 8; nt++) {
                const unsigned* Vr = &Vt[(nt * 8 + g) * ATS + k8 * 8 + qd];
                unsigned b0 = Vr[0];
                unsigned b1 = Vr[4];
                pgqa_mma_tf32(oacc[nt][0], oacc[nt][1], oacc[nt][2], oacc[nt][3],
                              pa0, pa1, pa2, pa3, b0, b1);
            }
        }
        __syncthreads();
    }

    float inv0 = 1.f / lr0, inv1 = 1.f / lr1;
    float* O0 = Out + ((size_t)(b * NP + q0 + wm + g)) * PD + h * HD;
    float* O1 = Out + ((size_t)(b * NP + q0 + wm + g + 8)) * PD + h * HD;
#pragma unroll
    for (int nt = 0; nt < 8; nt++) {
        *(float2*)(O0 + nt * 8 + qd * 2) =
            make_float2(oacc[nt][0] * inv0, oacc[nt][1] * inv0);
        *(float2*)(O1 + nt * 8 + qd * 2) =
            make_float2(oacc[nt][2] * inv1, oacc[nt][3] * inv1);
    }
}

// -------- M noise: zero accum -> parallel gen+partial stats -> finalize ------
__global__ void pgqa_mzero() {
    int t = threadIdx.x;
    if (t < NH) { pgqa_msum[t] = 0.0; pgqa_msum2[t] = 0.0; }
}

__global__ void pgqa_mgen() {
    const int h = blockIdx.x >> 3;         // 0..11
    const int seg = blockIdx.x & 7;        // 0..7, 8192 elems each
    const int tid = threadIdx.x;           // 256
    double s = 0.0, s2 = 0.0;
    unsigned base = (unsigned)h * YLEN + seg * 8192;
    for (unsigned k = tid; k < 8192; k += 256) {
        unsigned c = seg * 8192 + k;
        unsigned i = (unsigned)h * YLEN + c;
        float mv = pgqa_m_at(i);
        if (c == (unsigned)(h & 1)) mv = 0.f;    // zeroed diagonal element
        pgqa_M[i] = mv;
        s += mv; s2 += (double)mv * mv;
    }
    (void)base;
    __shared__ double shs[256], shs2[256];
    shs[tid] = s; shs2[tid] = s2; __syncthreads();
    for (int st = 128; st > 0; st >>= 1) {
        if (tid < st) { shs[tid] += shs[tid + st]; shs2[tid] += shs2[tid + st]; }
        __syncthreads();
    }
    if (tid == 0) {
        atomicAdd(&pgqa_msum[h], shs[0]);
        atomicAdd(&pgqa_msum2[h], shs2[0]);
    }
}

__global__ void pgqa_mfin() {
    int h = threadIdx.x;
    if (h < NH) {
        double n = (double)YLEN;
        double sm = pgqa_msum[h], sm2 = pgqa_msum2[h];
        double mean = sm / n;
        double var = (sm2 - sm * sm / n) / (n - 1.0);
        double sd = sqrt(var > 0.0 ? var : 0.0);
        if (sd == 0.0) sd = 1.0;
        pgqa_mmean[h] = (float)mean;
        pgqa_mistd[h] = (float)(1.0 / sd);
    }
}

// ---------------- per (b,h) row stats of att ---------------------------------
__global__ void pgqa_rstats(const float* __restrict__ Att) {
    const int bh = blockIdx.x, b = bh / NH, h = bh % NH;
    const int tid = threadIdx.x;   // 256
    const float* base = Att + (size_t)b * NP * PD + h * HD;
    const int d = tid & 63, p0 = tid >> 6;
    double s = 0.0, s2 = 0.0;
    for (int p = p0; p < NP; p += 4) {
        float v = base[(size_t)p * PD + d];
        s += v; s2 += (double)v * v;
    }
    __shared__ double shs[256], shs2[256];
    shs[tid] = s; shs2[tid] = s2; __syncthreads();
    for (int st = 128; st > 0; st >>= 1) {
        if (tid < st) { shs[tid] += shs[tid + st]; shs2[tid] += shs2[tid + st]; }
        __syncthreads();
    }
    if (tid == 0) {
        double n = (double)YLEN;
        double mean = shs[0] / n;
        double var = (shs2[0] - shs[0] * shs[0] / n) / (n - 1.0);
        pgqa_rmean[bh] = (float)mean;
        pgqa_rstd[bh] = (float)sqrt(var > 0.0 ? var : 0.0);
    }
}

// ---------------- launcher ---------------------------------------------------
extern "C" void kernel_launch(void* const* d_in, const int* in_sizes, int n_in,
                              void* d_out, int out_size) {
    const float* x  = (const float*)d_in[0];
    const float* Wq = (const float*)d_in[1];
    const float* Wk = (const float*)d_in[2];
    const float* Wv = (const float*)d_in[3];
    const float* Wp = (const float*)d_in[4];
    const float* bp = (const float*)d_in[5];
    float* out = (float*)d_out;

    float *Qb, *Kb, *Vb, *Ab;
    cudaGetSymbolAddress((void**)&Qb, pgqa_Q);
    cudaGetSymbolAddress((void**)&Kb, pgqa_K);
    cudaGetSymbolAddress((void**)&Vb, pgqa_V);
    cudaGetSymbolAddress((void**)&Ab, pgqa_Att);

    const int ATTN_SMEM = 3 * 64 * ATS * 4;   // 52224 B
    cudaFuncSetAttribute(pgqa_attn_mma, cudaFuncAttributeMaxDynamicSharedMemorySize, ATTN_SMEM);

    // M noise stats (independent of everything; M needed only by final GEMM)
    pgqa_mzero<<<1, 32>>>();
    pgqa_mgen<<<96, 256>>>();
    pgqa_mfin<<<1, 32>>>();

    // q/k/v projections on tensor cores (q pre-scaled by 1/sqrt(64))
    pgqa_gemm_mma<false><<<dim3(PD / 128, BPROWS / 128), 256>>>(x, Wq, nullptr, Qb, PD, PD, 0.125f);
    pgqa_gemm_mma<false><<<dim3(KVDIM / 128, BPROWS / 128), 256>>>(x, Wk, nullptr, Kb, KVDIM, PD, 1.0f);
    pgqa_gemm_mma<false><<<dim3(KVDIM / 128, BPROWS / 128), 256>>>(x, Wv, nullptr, Vb, KVDIM, PD, 1.0f);

    // flash attention on tensor cores
    pgqa_attn_mma<<<dim3(NP / 64, NB * NH), 128, ATTN_SMEM>>>(Qb, Kb, Vb, Ab);

    // per (b,h) stats of att
    pgqa_rstats<<<NB * NH, 256>>>(Ab);

    // output projection (+bias) with noise subtraction fused into A load
    pgqa_gemm_mma<true><<<dim3(PD / 128, BPROWS / 128), 256>>>(Ab, Wp, bp, out, PD, PD, 1.0f);
}

// round 10
// speedup vs baseline: 2.9051x; 1.3767x over previous
#include <cuda_runtime.h>
#include <math.h>
#include <stdint.h>

// Problem constants
#define PD   768        // model dim
#define NB   8          // batch
#define NP   1024       // seq len
#define NH   12         // heads
#define NKV  6          // kv heads
#define HD   64         // head dim
#define BPROWS (NB*NP)          // 8192
#define KVDIM  (NKV*HD)         // 384
#define YLEN   (NP*HD)          // 65536
#define MTOT   (NH*YLEN)        // 786432

// ---------------- scratch (static device memory; no allocations) -------------
__device__ float pgqa_Q[BPROWS*PD];      // scaled q, [B*P, 768]
__device__ float pgqa_K[BPROWS*KVDIM];   // [B*P, 384]
__device__ float pgqa_V[BPROWS*KVDIM];
__device__ float pgqa_Att[BPROWS*PD];    // attention out, [B*P, 768]
__device__ float pgqa_M[MTOT];           // regenerated uniform matrix [12, 65536]
__device__ float pgqa_rmean[NB*NH];
__device__ float pgqa_rstd[NB*NH];
__device__ float pgqa_mmean[NH];
__device__ float pgqa_mistd[NH];
__device__ double pgqa_msum[NH];
__device__ double pgqa_msum2[NH];

// ---------------- JAX threefry2x32, key = (0, 42) ----------------------------
__device__ __forceinline__ void pgqa_threefry(unsigned x0, unsigned x1,
                                              unsigned& o0, unsigned& o1) {
    const unsigned ks0 = 0u, ks1 = 42u, ks2 = 0x1BD11BDAu ^ 42u;
    x0 += ks0; x1 += ks1;
#define PGQA_R(r) { x0 += x1; x1 = (x1 << (r)) | (x1 >> (32 - (r))); x1 ^= x0; }
    PGQA_R(13) PGQA_R(15) PGQA_R(26) PGQA_R(6)
    x0 += ks1; x1 += ks2 + 1u;
    PGQA_R(17) PGQA_R(29) PGQA_R(16) PGQA_R(24)
    x0 += ks2; x1 += ks0 + 2u;
    PGQA_R(13) PGQA_R(15) PGQA_R(26) PGQA_R(6)
    x0 += ks0; x1 += ks1 + 3u;
    PGQA_R(17) PGQA_R(29) PGQA_R(16) PGQA_R(24)
    x0 += ks1; x1 += ks2 + 4u;
    PGQA_R(13) PGQA_R(15) PGQA_R(26) PGQA_R(6)
    x0 += ks2; x1 += ks0 + 5u;
#undef PGQA_R
    o0 = x0; o1 = x1;
}
__device__ __forceinline__ float pgqa_uniform(unsigned bits) {
    return __uint_as_float((bits >> 9) | 0x3f800000u) - 1.0f;
}
__device__ __forceinline__ float pgqa_m_at(unsigned i) {
    unsigned o0, o1;
    pgqa_threefry(0u, i, o0, o1);
    return pgqa_uniform(o0 ^ o1);
}

__device__ __forceinline__ unsigned pgqa_tf32r(float f) {
    unsigned u; asm("cvt.rna.tf32.f32 %0, %1;" : "=r"(u) : "f"(f)); return u;
}
__device__ __forceinline__ void pgqa_mma_tf32(float& c0, float& c1, float& c2, float& c3,
                                              unsigned a0, unsigned a1, unsigned a2, unsigned a3,
                                              unsigned b0, unsigned b1) {
    asm volatile(
        "mma.sync.aligned.m16n8k8.row.col.f32.tf32.tf32.f32 "
        "{%0,%1,%2,%3}, {%4,%5,%6,%7}, {%8,%9}, {%0,%1,%2,%3};"
        : "+f"(c0), "+f"(c1), "+f"(c2), "+f"(c3)
        : "r"(a0), "r"(a1), "r"(a2), "r"(a3), "r"(b0), "r"(b1));
}
__device__ __forceinline__ uint32_t pgqa_s2u(const void* p) {
    uint32_t a;
    asm("{ .reg .u64 t; cvta.to.shared.u64 t, %1; cvt.u32.u64 %0, t; }" : "=r"(a) : "l"(p));
    return a;
}
__device__ __forceinline__ void pgqa_cp16(uint32_t dst, const void* src) {
    asm volatile("cp.async.ca.shared.global [%0], [%1], 16;" :: "r"(dst), "l"(src));
}

// ============== mma.sync tf32 GEMM, cp.async double-buffered =================
// Block tile 128x128, BK=32, 256 thr = 8 warps (2x4), warp tile 64x32.
// Raw fp32 in smem; tf32 cvt at fragment load. FUSE_NOISE: manual A path.
#define GAS 36     // As stride (floats): bank = (4m+k)%32 -> conflict-free
#define GBS 136    // Bs stride (floats): bank = (8k+n)%32 -> conflict-free
#define GA_SZ (128 * GAS)
#define GB_SZ (32 * GBS)
#define GSMEM_BYTES ((2 * GA_SZ + 2 * GB_SZ) * 4)

template<bool FUSE_NOISE>
__global__ __launch_bounds__(256)
void pgqa_gemm_mma(const float* __restrict__ A, const float* __restrict__ B,
                   const float* __restrict__ bias, float* __restrict__ C,
                   int N, int K, float alpha) {
    extern __shared__ float gsm[];
    float* Af0 = gsm;
    float* Bf0 = gsm + 2 * GA_SZ;
    const uint32_t sb = pgqa_s2u(gsm);
    const int t = threadIdx.x, warp = t >> 5, lane = t & 31;
    const int g = lane >> 2, q = lane & 3;
    const int wm = (warp >> 2) * 64, wn = (warp & 3) * 32;
    const int m0 = blockIdx.y * 128, col0 = blockIdx.x * 128;
    const int NC = K >> 5;

    float acc[4][4][4];
#pragma unroll
    for (int i = 0; i < 4; i++)
#pragma unroll
        for (int j = 0; j < 4; j++) {
            acc[i][j][0] = 0.f; acc[i][j][1] = 0.f;
            acc[i][j][2] = 0.f; acc[i][j][3] = 0.f;
        }

    // tile load issue (A: 128x32, B: 32x128) into buffer `buf`
    auto issue_tile = [&](int c, int buf) {
        const int kc0 = c << 5;
        float* Ab = Af0 + buf * GA_SZ;
        float* Bb = Bf0 + buf * GB_SZ;
#pragma unroll
        for (int i = 0; i < 4; i++) {
            int idx = t + (i << 8);
            int r = idx >> 3, j = (idx & 7) << 2;
            const float* src = A + (size_t)(m0 + r) * K + kc0 + j;
            if (!FUSE_NOISE) {
                pgqa_cp16(sb + (uint32_t)(buf * GA_SZ + r * GAS + j) * 4, src);
            } else {
                float4 v = *(const float4*)src;
                int cgl = kc0 + j;
                int hh = cgl >> 6, dd = cgl & 63;
                int rg = m0 + r;
                int pp = rg & (NP - 1);
                int bh = (rg >> 10) * NH + hh;
                float4 mv = *(const float4*)(pgqa_M + ((size_t)hh << 16) + (pp << 6) + dd);
                float im = pgqa_mmean[hh], is = pgqa_mistd[hh];
                float rs = pgqa_rstd[bh], rm = pgqa_rmean[bh];
                v.x -= (mv.x - im) * is * rs + rm;
                v.y -= (mv.y - im) * is * rs + rm;
                v.z -= (mv.z - im) * is * rs + rm;
                v.w -= (mv.w - im) * is * rs + rm;
                *(float4*)&Ab[r * GAS + j] = v;
            }
        }
#pragma unroll
        for (int i = 0; i < 4; i++) {
            int idx = t + (i << 8);
            int r = idx >> 5, j = (idx & 31) << 2;
            pgqa_cp16(sb + (uint32_t)(2 * GA_SZ + buf * GB_SZ + r * GBS + j) * 4,
                      B + (size_t)(kc0 + r) * N + col0 + j);
        }
        (void)Bb;
    };

    issue_tile(0, 0);
    asm volatile("cp.async.commit_group;" ::: "memory");

    for (int c = 0; c < NC; ++c) {
        if (c + 1 < NC) {
            issue_tile(c + 1, (c + 1) & 1);
            asm volatile("cp.async.commit_group;" ::: "memory");
            asm volatile("cp.async.wait_group 1;" ::: "memory");
        } else {
            asm volatile("cp.async.wait_group 0;" ::: "memory");
        }
        __syncthreads();

        const float* Ab = Af0 + (c & 1) * GA_SZ;
        const float* Bb = Bf0 + (c & 1) * GB_SZ;
#pragma unroll
        for (int k8 = 0; k8 < 32; k8 += 8) {
            unsigned a[4][4];
#pragma unroll
            for (int mt = 0; mt < 4; mt++) {
                const float* Ar = &Ab[(wm + mt * 16 + g) * GAS + k8 + q];
                a[mt][0] = pgqa_tf32r(Ar[0]);
                a[mt][1] = pgqa_tf32r(Ar[8 * GAS]);
                a[mt][2] = pgqa_tf32r(Ar[4]);
                a[mt][3] = pgqa_tf32r(Ar[8 * GAS + 4]);
            }
#pragma unroll
            for (int nt = 0; nt < 4; nt++) {
                const float* Br = &Bb[(k8 + q) * GBS + wn + nt * 8 + g];
                unsigned b0 = pgqa_tf32r(Br[0]);
                unsigned b1 = pgqa_tf32r(Br[4 * GBS]);
#pragma unroll
                for (int mt = 0; mt < 4; mt++)
                    pgqa_mma_tf32(acc[mt][nt][0], acc[mt][nt][1],
                                  acc[mt][nt][2], acc[mt][nt][3],
                                  a[mt][0], a[mt][1], a[mt][2], a[mt][3], b0, b1);
            }
        }
        __syncthreads();   // all warps done with buf (c&1) before reload
    }

#pragma unroll
    for (int mt = 0; mt < 4; mt++) {
        int r0 = m0 + wm + mt * 16 + g;
#pragma unroll
        for (int nt = 0; nt < 4; nt++) {
            int c = col0 + wn + nt * 8 + q * 2;
            float b0 = 0.f, b1 = 0.f;
            if (bias) { b0 = bias[c]; b1 = bias[c + 1]; }
            *(float2*)(C + (size_t)r0 * N + c) =
                make_float2(acc[mt][nt][0] * alpha + b0, acc[mt][nt][1] * alpha + b1);
            *(float2*)(C + (size_t)(r0 + 8) * N + c) =
                make_float2(acc[mt][nt][2] * alpha + b0, acc[mt][nt][3] * alpha + b1);
        }
    }
}

// ============== mma.sync tf32 flash GQA attention, paired heads ==============
// grid (P/64, B*KV); 256 thr = 8 warps. Warps 0-3: head 2kv, warps 4-7: head
// 2kv+1; both share the K/V tiles. Warp owns 16 q-rows. K-tile = 64.
#define ATS 68   // smem stride: bank = (4row+col)%32 -> conflict-free frags
#define ATTN_SMEM_BYTES ((64 + 64 + 128) * ATS * 4)

__global__ __launch_bounds__(256)
void pgqa_attn_mma(const float* __restrict__ Q, const float* __restrict__ K,
                   const float* __restrict__ V, float* __restrict__ Out) {
    extern __shared__ unsigned smu[];
    unsigned* Ks = smu;                  // [64][ATS]  K[kpos][d]
    unsigned* Vt = smu + 64 * ATS;       // [64][ATS]  V^T[d][kpos]
    unsigned* Ps = smu + 2 * 64 * ATS;   // [128][ATS] Q staging / P, rows per head

    const int t = threadIdx.x, warp = t >> 5, lane = t & 31;
    const int g = lane >> 2, qd = lane & 3;
    const int b = blockIdx.y / NKV, kvh = blockIdx.y % NKV;
    const int hsel = warp >> 2, h = kvh * 2 + hsel;
    const int q0 = blockIdx.x * 64, wm = (warp & 3) * 16;
    const int hb = hsel * 64 + wm;       // this warp's row base in Ps

    const float* Kg = K + (size_t)b * NP * KVDIM + kvh * HD;
    const float* Vg = V + (size_t)b * NP * KVDIM + kvh * HD;

    // stage Q for both heads: Ps row r: head kvh*2 + (r>>6), q-row q0+(r&63)
    {
        int r = t >> 1, c0 = (t & 1) * 32;
        const float* src = Q + ((size_t)(b * NP + q0 + (r & 63))) * PD
                         + (kvh * 2 + (r >> 6)) * HD + c0;
#pragma unroll
        for (int j = 0; j < 8; j++) {
            float4 v = *(const float4*)(src + j * 4);
            unsigned* dst = &Ps[r * ATS + c0 + j * 4];
            dst[0] = pgqa_tf32r(v.x); dst[1] = pgqa_tf32r(v.y);
            dst[2] = pgqa_tf32r(v.z); dst[3] = pgqa_tf32r(v.w);
        }
    }
    __syncthreads();
    unsigned qa[8][4];
#pragma unroll
    for (int k8 = 0; k8 < 8; k8++) {
        const unsigned* A0 = &Ps[(hb + g) * ATS + k8 * 8 + qd];
        const unsigned* A1 = &Ps[(hb + g + 8) * ATS + k8 * 8 + qd];
        qa[k8][0] = A0[0]; qa[k8][1] = A1[0]; qa[k8][2] = A0[4]; qa[k8][3] = A1[4];
    }
    __syncthreads();

    float oacc[8][4];
#pragma unroll
    for (int nt = 0; nt < 8; nt++) {
        oacc[nt][0] = 0.f; oacc[nt][1] = 0.f; oacc[nt][2] = 0.f; oacc[nt][3] = 0.f;
    }
    float mr0 = -1e30f, mr1 = -1e30f, lr0 = 0.f, lr1 = 0.f;

    for (int tk = 0; tk < NP / 64; tk++) {
        // K tile (K-major) and V tile (transposed); 256 thr, 16 floats each
        {
            int r = t >> 2, c0 = (t & 3) * 16;
            const float* ksrc = Kg + (size_t)(tk * 64 + r) * KVDIM + c0;
            const float* vsrc = Vg + (size_t)(tk * 64 + r) * KVDIM + c0;
#pragma unroll
            for (int j = 0; j < 4; j++) {
                float4 v = *(const float4*)(ksrc + j * 4);
                unsigned* dst = &Ks[r * ATS + c0 + j * 4];
                dst[0] = pgqa_tf32r(v.x); dst[1] = pgqa_tf32r(v.y);
                dst[2] = pgqa_tf32r(v.z); dst[3] = pgqa_tf32r(v.w);
                float4 w = *(const float4*)(vsrc + j * 4);
                int d0 = c0 + j * 4;
                Vt[(d0 + 0) * ATS + r] = pgqa_tf32r(w.x);
                Vt[(d0 + 1) * ATS + r] = pgqa_tf32r(w.y);
                Vt[(d0 + 2) * ATS + r] = pgqa_tf32r(w.z);
                Vt[(d0 + 3) * ATS + r] = pgqa_tf32r(w.w);
            }
        }
        __syncthreads();

        // S = Q K^T
        float sacc[8][4];
#pragma unroll
        for (int nt = 0; nt < 8; nt++) {
            sacc[nt][0] = 0.f; sacc[nt][1] = 0.f; sacc[nt][2] = 0.f; sacc[nt][3] = 0.f;
        }
#pragma unroll
        for (int nt = 0; nt < 8; nt++) {
            const unsigned* Kr = &Ks[(nt * 8 + g) * ATS];
#pragma unroll
            for (int k8 = 0; k8 < 8; k8++) {
                unsigned b0 = Kr[k8 * 8 + qd];
                unsigned b1 = Kr[k8 * 8 + qd + 4];
                pgqa_mma_tf32(sacc[nt][0], sacc[nt][1], sacc[nt][2], sacc[nt][3],
                              qa[k8][0], qa[k8][1], qa[k8][2], qa[k8][3], b0, b1);
            }
        }

        // online softmax (rows g, g+8 of warp tile); quad lanes share rows
        float mx0 = fmaxf(sacc[0][0], sacc[0][1]);
        float mx1 = fmaxf(sacc[0][2], sacc[0][3]);
#pragma unroll
        for (int nt = 1; nt < 8; nt++) {
            mx0 = fmaxf(mx0, fmaxf(sacc[nt][0], sacc[nt][1]));
            mx1 = fmaxf(mx1, fmaxf(sacc[nt][2], sacc[nt][3]));
        }
        mx0 = fmaxf(mx0, __shfl_xor_sync(~0u, mx0, 1));
        mx0 = fmaxf(mx0, __shfl_xor_sync(~0u, mx0, 2));
        mx1 = fmaxf(mx1, __shfl_xor_sync(~0u, mx1, 1));
        mx1 = fmaxf(mx1, __shfl_xor_sync(~0u, mx1, 2));
        float mn0 = fmaxf(mr0, mx0), mn1 = fmaxf(mr1, mx1);
        float corr0 = __expf(mr0 - mn0), corr1 = __expf(mr1 - mn1);
        float s0 = 0.f, s1 = 0.f;
        unsigned* P0 = &Ps[(hb + g) * ATS + qd * 2];
        unsigned* P1 = &Ps[(hb + g + 8) * ATS + qd * 2];
#pragma unroll
        for (int nt = 0; nt < 8; nt++) {
            float p0 = __expf(sacc[nt][0] - mn0);
            float p1 = __expf(sacc[nt][1] - mn0);
            float p2 = __expf(sacc[nt][2] - mn1);
            float p3 = __expf(sacc[nt][3] - mn1);
            s0 += p0 + p1; s1 += p2 + p3;
            P0[nt * 8 + 0] = pgqa_tf32r(p0); P0[nt * 8 + 1] = pgqa_tf32r(p1);
            P1[nt * 8 + 0] = pgqa_tf32r(p2); P1[nt * 8 + 1] = pgqa_tf32r(p3);
            oacc[nt][0] *= corr0; oacc[nt][1] *= corr0;
            oacc[nt][2] *= corr1; oacc[nt][3] *= corr1;
        }
        s0 += __shfl_xor_sync(~0u, s0, 1); s0 += __shfl_xor_sync(~0u, s0, 2);
        s1 += __shfl_xor_sync(~0u, s1, 1); s1 += __shfl_xor_sync(~0u, s1, 2);
        lr0 = lr0 * corr0 + s0; lr1 = lr1 * corr1 + s1;
        mr0 = mn0; mr1 = mn1;
        __syncwarp();   // P round-trip is intra-warp (cross-lane) only

        // O += P V
#pragma unroll
        for (int k8 = 0; k8 < 8; k8++) {
            const unsigned* A0 = &Ps[(hb + g) * ATS + k8 * 8 + qd];
            const unsigned* A1 = &Ps[(hb + g + 8) * ATS + k8 * 8 + qd];
            unsigned pa0 = A0[0], pa1 = A1[0], pa2 = A0[4], pa3 = A1[4];
#pragma unroll
            for (int nt = 0; nt < 8; nt++) {
                const unsigned* Vr = &Vt[(nt * 8 + g) * ATS + k8 * 8 + qd];
                unsigned b0 = Vr[0];
                unsigned b1 = Vr[4];
                pgqa_mma_tf32(oacc[nt][0], oacc[nt][1], oacc[nt][2], oacc[nt][3],
                              pa0, pa1, pa2, pa3, b0, b1);
            }
        }
        __syncthreads();   // done with Ks/Vt before next tile load
    }

    float inv0 = 1.f / lr0, inv1 = 1.f / lr1;
    float* O0 = Out + ((size_t)(b * NP + q0 + wm + g)) * PD + h * HD;
    float* O1 = Out + ((size_t)(b * NP + q0 + wm + g + 8)) * PD + h * HD;
#pragma unroll
    for (int nt = 0; nt < 8; nt++) {
        *(float2*)(O0 + nt * 8 + qd * 2) =
            make_float2(oacc[nt][0] * inv0, oacc[nt][1] * inv0);
        *(float2*)(O1 + nt * 8 + qd * 2) =
            make_float2(oacc[nt][2] * inv1, oacc[nt][3] * inv1);
    }
}

// -------- M noise: zero accum -> parallel gen+partial stats -> finalize ------
__global__ void pgqa_mzero() {
    int t = threadIdx.x;
    if (t < NH) { pgqa_msum[t] = 0.0; pgqa_msum2[t] = 0.0; }
}

__global__ void pgqa_mgen() {
    const int h = blockIdx.x >> 3;         // 0..11
    const int seg = blockIdx.x & 7;        // 0..7
    const int tid = threadIdx.x;           // 256
    double s = 0.0, s2 = 0.0;
    for (unsigned k = tid; k < 8192; k += 256) {
        unsigned c = seg * 8192 + k;
        unsigned i = (unsigned)h * YLEN + c;
        float mv = pgqa_m_at(i);
        if (c == (unsigned)(h & 1)) mv = 0.f;
        pgqa_M[i] = mv;
        s += mv; s2 += (double)mv * mv;
    }
    __shared__ double shs[256], shs2[256];
    shs[tid] = s; shs2[tid] = s2; __syncthreads();
    for (int st = 128; st > 0; st >>= 1) {
        if (tid < st) { shs[tid] += shs[tid + st]; shs2[tid] += shs2[tid + st]; }
        __syncthreads();
    }
    if (tid == 0) {
        atomicAdd(&pgqa_msum[h], shs[0]);
        atomicAdd(&pgqa_msum2[h], shs2[0]);
    }
}

__global__ void pgqa_mfin() {
    int h = threadIdx.x;
    if (h < NH) {
        double n = (double)YLEN;
        double sm = pgqa_msum[h], sm2 = pgqa_msum2[h];
        double mean = sm / n;
        double var = (sm2 - sm * sm / n) / (n - 1.0);
        double sd = sqrt(var > 0.0 ? var : 0.0);
        if (sd == 0.0) sd = 1.0;
        pgqa_mmean[h] = (float)mean;
        pgqa_mistd[h] = (float)(1.0 / sd);
    }
}

// ---------------- per (b,h) row stats of att ---------------------------------
__global__ void pgqa_rstats(const float* __restrict__ Att) {
    const int bh = blockIdx.x, b = bh / NH, h = bh % NH;
    const int tid = threadIdx.x;   // 256
    const float* base = Att + (size_t)b * NP * PD + h * HD;
    const int d = tid & 63, p0 = tid >> 6;
    double s = 0.0, s2 = 0.0;
    for (int p = p0; p < NP; p += 4) {
        float v = base[(size_t)p * PD + d];
        s += v; s2 += (double)v * v;
    }
    __shared__ double shs[256], shs2[256];
    shs[tid] = s; shs2[tid] = s2; __syncthreads();
    for (int st = 128; st > 0; st >>= 1) {
        if (tid < st) { shs[tid] += shs[tid + st]; shs2[tid] += shs2[tid + st]; }
        __syncthreads();
    }
    if (tid == 0) {
        double n = (double)YLEN;
        double mean = shs[0] / n;
        double var = (shs2[0] - shs[0] * shs[0] / n) / (n - 1.0);
        pgqa_rmean[bh] = (float)mean;
        pgqa_rstd[bh] = (float)sqrt(var > 0.0 ? var : 0.0);
    }
}

// ---------------- launcher ---------------------------------------------------
extern "C" void kernel_launch(void* const* d_in, const int* in_sizes, int n_in,
                              void* d_out, int out_size) {
    const float* x  = (const float*)d_in[0];
    const float* Wq = (const float*)d_in[1];
    const float* Wk = (const float*)d_in[2];
    const float* Wv = (const float*)d_in[3];
    const float* Wp = (const float*)d_in[4];
    const float* bp = (const float*)d_in[5];
    float* out = (float*)d_out;

    float *Qb, *Kb, *Vb, *Ab;
    cudaGetSymbolAddress((void**)&Qb, pgqa_Q);
    cudaGetSymbolAddress((void**)&Kb, pgqa_K);
    cudaGetSymbolAddress((void**)&Vb, pgqa_V);
    cudaGetSymbolAddress((void**)&Ab, pgqa_Att);

    cudaFuncSetAttribute(pgqa_attn_mma, cudaFuncAttributeMaxDynamicSharedMemorySize, ATTN_SMEM_BYTES);
    cudaFuncSetAttribute(pgqa_gemm_mma<false>, cudaFuncAttributeMaxDynamicSharedMemorySize, GSMEM_BYTES);
    cudaFuncSetAttribute(pgqa_gemm_mma<true>,  cudaFuncAttributeMaxDynamicSharedMemorySize, GSMEM_BYTES);

    // M noise stats (independent; M needed only by final GEMM)
    pgqa_mzero<<<1, 32>>>();
    pgqa_mgen<<<96, 256>>>();
    pgqa_mfin<<<1, 32>>>();

    // q/k/v projections (q pre-scaled by 1/sqrt(64))
    pgqa_gemm_mma<false><<<dim3(PD / 128, BPROWS / 128), 256, GSMEM_BYTES>>>(
        x, Wq, nullptr, Qb, PD, PD, 0.125f);
    pgqa_gemm_mma<false><<<dim3(KVDIM / 128, BPROWS / 128), 256, GSMEM_BYTES>>>(
        x, Wk, nullptr, Kb, KVDIM, PD, 1.0f);
    pgqa_gemm_mma<false><<<dim3(KVDIM / 128, BPROWS / 128), 256, GSMEM_BYTES>>>(
        x, Wv, nullptr, Vb, KVDIM, PD, 1.0f);

    // flash attention, paired heads per KV group
    pgqa_attn_mma<<<dim3(NP / 64, NB * NKV), 256, ATTN_SMEM_BYTES>>>(Qb, Kb, Vb, Ab);

    // per (b,h) stats of att
    pgqa_rstats<<<NB * NH, 256>>>(Ab);

    // output projection (+bias) with noise subtraction fused into A load
    pgqa_gemm_mma<true><<<dim3(PD / 128, BPROWS / 128), 256, GSMEM_BYTES>>>(
        Ab, Wp, bp, out, PD, PD, 1.0f);
}